// round 14
// baseline (speedup 1.0000x reference)
#include <cuda_runtime.h>
#include <cuda_fp16.h>
#include <cstdint>

#define S_LEN  2048
#define G_GRP  2
#define EMB    1024
#define NKV    4
#define HD     64
#define MROWS  (S_LEN * G_GRP)      // 4096
#define KVW    (NKV * HD)           // 256
#define ROWQ   (G_GRP * EMB)        // 2048 (halves)
#define ROWK   (G_GRP * KVW)        // 512  (halves)

// ---------------- scratch (all fp16) ----------------
__device__ __half g_X[MROWS * EMB];
__device__ __half g_Q[MROWS * EMB];                 // pre-scaled by SC
__device__ __half g_K[MROWS * KVW];
__device__ __half g_V[MROWS * KVW];                 // natural [m][kvh*64+d]
__device__ __half g_O[MROWS * EMB];
__device__ __half g_WT[(EMB + 2 * KVW) * EMB];
__device__ __half g_WoT[EMB * EMB];

#define SC_CONST (0.125f * 1.4426950408889634f)

// ================= helpers =================
__device__ __forceinline__ uint32_t smem_u32(const void* p) {
    uint32_t a;
    asm("{ .reg .u64 t; cvta.to.shared.u64 t, %1; cvt.u32.u64 %0, t; }" : "=r"(a) : "l"(p));
    return a;
}
__device__ __forceinline__ void mma_f16(float c[4], const uint32_t a[4], const uint32_t b[2]) {
    asm volatile(
        "mma.sync.aligned.m16n8k16.row.col.f32.f16.f16.f32 "
        "{%0,%1,%2,%3}, {%4,%5,%6,%7}, {%8,%9}, {%0,%1,%2,%3};"
        : "+f"(c[0]), "+f"(c[1]), "+f"(c[2]), "+f"(c[3])
        : "r"(a[0]), "r"(a[1]), "r"(a[2]), "r"(a[3]), "r"(b[0]), "r"(b[1]));
}
__device__ __forceinline__ void ldsm_x4(uint32_t r[4], uint32_t addr) {
    asm volatile("ldmatrix.sync.aligned.m8n8.x4.shared.b16 {%0,%1,%2,%3}, [%4];"
        : "=r"(r[0]), "=r"(r[1]), "=r"(r[2]), "=r"(r[3]) : "r"(addr));
}
__device__ __forceinline__ void ldsm_x4_t(uint32_t r[4], uint32_t addr) {
    asm volatile("ldmatrix.sync.aligned.m8n8.x4.trans.shared.b16 {%0,%1,%2,%3}, [%4];"
        : "=r"(r[0]), "=r"(r[1]), "=r"(r[2]), "=r"(r[3]) : "r"(addr));
}
__device__ __forceinline__ int ldsmA_off(int lane, int stride) {
    return ((lane & 7) + ((lane >> 3) & 1) * 8) * stride + ((lane >> 4) & 1) * 8;
}
__device__ __forceinline__ int ldsmB_off(int lane, int stride) {
    return ((lane & 7) + ((lane >> 4) & 1) * 8) * stride + ((lane >> 3) & 1) * 8;
}
__device__ __forceinline__ void cpa16(uint32_t dst, const void* src) {
    asm volatile("cp.async.cg.shared.global [%0], [%1], 16;" :: "r"(dst), "l"(src));
}
__device__ __forceinline__ void cpa_commit() { asm volatile("cp.async.commit_group;"); }
template <int N>
__device__ __forceinline__ void cpa_wait() { asm volatile("cp.async.wait_group %0;" :: "n"(N)); }
__device__ __forceinline__ uint32_t h2u(__half2 h) { return *reinterpret_cast<uint32_t*>(&h); }
__device__ __forceinline__ uint32_t h2exp2(uint32_t x) {
    uint32_t r;
    asm("ex2.approx.f16x2 %0, %1;" : "=r"(r) : "r"(x));
    return r;
}

// ================= fused prep: X round + all weight transposes ===============
__global__ __launch_bounds__(256) void prep_all(
    const float* __restrict__ x,
    const float* __restrict__ Wq, const float* __restrict__ Wk,
    const float* __restrict__ Wv, const float* __restrict__ Wo)
{
    __shared__ float t[32][33];
    const int b = blockIdx.x;
    if (b < 2048) {
        size_t i = (size_t)b * 256 + threadIdx.x;
        const float4* src = reinterpret_cast<const float4*>(x) + 2 * i;
        float4 v0 = src[0], v1 = src[1];
        __half2* dst = reinterpret_cast<__half2*>(g_X) + 4 * i;
        dst[0] = __floats2half2_rn(v0.x, v0.y);
        dst[1] = __floats2half2_rn(v0.z, v0.w);
        dst[2] = __floats2half2_rn(v1.x, v1.y);
        dst[3] = __floats2half2_rn(v1.z, v1.w);
        return;
    }
    const int bb = b - 2048;
    const int bx = bb % 80;
    const int by = bb / 80;
    const float* W; __half* WT; int N; int nb;
    if (bx < 32)      { W = Wq; WT = g_WT;                               N = EMB; nb = bx; }
    else if (bx < 40) { W = Wk; WT = g_WT + (size_t)EMB * EMB;           N = KVW; nb = bx - 32; }
    else if (bx < 48) { W = Wv; WT = g_WT + (size_t)(EMB + KVW) * EMB;   N = KVW; nb = bx - 40; }
    else              { W = Wo; WT = g_WoT;                              N = EMB; nb = bx - 48; }

    const int tx  = threadIdx.x & 31;
    const int ty0 = threadIdx.x >> 5;
#pragma unroll
    for (int r = 0; r < 4; r++) {
        int ty = ty0 + r * 8;
        t[ty][tx] = W[(size_t)(by * 32 + ty) * N + nb * 32 + tx];
    }
    __syncthreads();
#pragma unroll
    for (int r = 0; r < 4; r++) {
        int ty = ty0 + r * 8;
        WT[(size_t)(nb * 32 + ty) * EMB + by * 32 + tx] = __float2half(t[tx][ty]);
    }
}

// ================= fp16 mma GEMM: 128x128 CTA, 64x64 warp tile ==============
#define AST 72
#define ABUF_H (128 * AST)
#define GEMM_SMEM (4 * ABUF_H * 2)    // 73728 B

// OM: 0 = fp32 out, 1 = half out, 2 = half out * SC
template <int OM>
__device__ __forceinline__ void gemm_tile(
    const __half* __restrict__ A, const __half* __restrict__ BT,
    void* __restrict__ Cv, int ldc, int m0, int n0bt, int c0)
{
    extern __shared__ __half hsm[];
    const uint32_t sb = smem_u32(hsm);

    const int tid  = threadIdx.x;
    const int lane = tid & 31;
    const int wid  = tid >> 5;
    const int wm   = wid >> 1;
    const int wn   = wid & 1;
    const int g    = lane >> 2;
    const int tg   = lane & 3;

    float acc[4][8][4];
#pragma unroll
    for (int mi = 0; mi < 4; mi++)
#pragma unroll
        for (int nt = 0; nt < 8; nt++)
#pragma unroll
            for (int j = 0; j < 4; j++) acc[mi][nt][j] = 0.0f;

    const int row = tid >> 3;
    const int q   = (tid & 7) * 8;

    auto stage = [&](int c, int buf) {
        const int k0 = c * 64;
        const uint32_t aBase = sb + (uint32_t)(2 * buf) * ABUF_H * 2;
        const uint32_t bBase = aBase + ABUF_H * 2;
#pragma unroll
        for (int t = 0; t < 8; t++) {
            int r = row + t * 16;
            cpa16(aBase + (uint32_t)(r * AST + q) * 2, &A [(size_t)(m0 + r) * EMB + k0 + q]);
            cpa16(bBase + (uint32_t)(r * AST + q) * 2, &BT[(size_t)(n0bt + r) * EMB + k0 + q]);
        }
    };

    uint32_t aOff[4], bOff[4];
    {
        const int la = ldsmA_off(lane, AST);
        const int lb = ldsmB_off(lane, AST);
#pragma unroll
        for (int mi = 0; mi < 4; mi++)
            aOff[mi] = (uint32_t)(((wm * 64 + mi * 16) * AST + la) * 2);
#pragma unroll
        for (int pr = 0; pr < 4; pr++)
            bOff[pr] = (uint32_t)(((wn * 64 + pr * 16) * AST + lb) * 2);
    }

    stage(0, 0); cpa_commit();

    for (int c = 0; c < 16; c++) {
        cpa_wait<0>();
        __syncthreads();
        if (c < 15) { stage(c + 1, (c + 1) & 1); cpa_commit(); }

        const uint32_t aBase = sb + (uint32_t)(2 * (c & 1)) * ABUF_H * 2;
        const uint32_t bBase = aBase + ABUF_H * 2;
#pragma unroll
        for (int kc = 0; kc < 4; kc++) {
            const uint32_t kkB = kc * 32;
            uint32_t a[4][4];
#pragma unroll
            for (int mi = 0; mi < 4; mi++)
                ldsm_x4(a[mi], aBase + aOff[mi] + kkB);
#pragma unroll
            for (int pr = 0; pr < 4; pr++) {
                uint32_t bfr[4];
                ldsm_x4(bfr, bBase + bOff[pr] + kkB);
#pragma unroll
                for (int mi = 0; mi < 4; mi++) {
                    mma_f16(acc[mi][pr * 2],     a[mi], bfr);
                    mma_f16(acc[mi][pr * 2 + 1], a[mi], bfr + 2);
                }
            }
        }
    }

#pragma unroll
    for (int mi = 0; mi < 4; mi++) {
        int r0 = m0 + wm * 64 + mi * 16 + g;
#pragma unroll
        for (int nt = 0; nt < 8; nt++) {
            int col = c0 + wn * 64 + nt * 8 + 2 * tg;
            if (OM == 0) {
                float* C = (float*)Cv;
                *reinterpret_cast<float2*>(&C[(size_t)r0 * ldc + col]) =
                    make_float2(acc[mi][nt][0], acc[mi][nt][1]);
                *reinterpret_cast<float2*>(&C[(size_t)(r0 + 8) * ldc + col]) =
                    make_float2(acc[mi][nt][2], acc[mi][nt][3]);
            } else {
                const float m = (OM == 2) ? SC_CONST : 1.0f;
                __half* C = (__half*)Cv;
                *reinterpret_cast<__half2*>(&C[(size_t)r0 * ldc + col]) =
                    __floats2half2_rn(acc[mi][nt][0] * m, acc[mi][nt][1] * m);
                *reinterpret_cast<__half2*>(&C[(size_t)(r0 + 8) * ldc + col]) =
                    __floats2half2_rn(acc[mi][nt][2] * m, acc[mi][nt][3] * m);
            }
        }
    }
}

__global__ __launch_bounds__(128, 3) void qkv_mma() {
    int nb = blockIdx.x;
    int m0 = blockIdx.y * 128;
    if (nb < 8)
        gemm_tile<2>(g_X, g_WT, g_Q, EMB, m0, nb * 128, nb * 128);
    else if (nb < 10)
        gemm_tile<1>(g_X, g_WT, g_K, KVW, m0, nb * 128, (nb - 8) * 128);
    else
        gemm_tile<1>(g_X, g_WT, g_V, KVW, m0, nb * 128, (nb - 10) * 128);
}

__global__ __launch_bounds__(128, 3) void oproj_mma(float* __restrict__ out) {
    gemm_tile<0>(g_O, g_WoT, out, EMB, blockIdx.y * 128, blockIdx.x * 128, blockIdx.x * 128);
}

// ================= flash attention: fp16 mma, trans-V, ones-MMA l ============
#define FST  72
#define TB_H (64 * FST)
#define FA_SMEM (4 * TB_H * 2)             // 36864 B

__global__ __launch_bounds__(256, 2) void flash_mma()
{
    extern __shared__ __half fsm[];
    const uint32_t sbK0 = smem_u32(fsm);
    const uint32_t sbV0 = sbK0 + 2 * TB_H * 2;

    const int tid  = threadIdx.x;
    const int lane = tid & 31;
    const int w    = tid >> 5;
    const int g    = lane >> 2;
    const int tg   = lane & 3;
    const int wr   = w * 16;

    const int gh  = blockIdx.x;
    const int qb  = (int)gridDim.y - 1 - blockIdx.y;
    const int grp = gh & 1;
    const int h   = gh >> 1;
    const int kvh = h >> 2;

    const __half* Qp = g_Q + grp * EMB + h * HD;
    const __half* Kp = g_K + grp * KVW + kvh * HD;
    const __half* Vp = g_V + grp * KVW + kvh * HD;
    __half*       Op = g_O + grp * EMB + h * HD;

    const int q0 = qb * 128;

    const int laA  = ldsmA_off(lane, FST);   // A-frags (Q) and trans-V B-frags
    const int laB  = ldsmB_off(lane, FST);   // K B-frags
    const uint32_t pOff = (uint32_t)((wr * FST + laA) * 2);
    uint32_t bOffK[4], bOffV[4];
#pragma unroll
    for (int pr = 0; pr < 4; pr++) {
        bOffK[pr] = (uint32_t)((pr * 16 * FST + laB) * 2);   // pr = k-row group (n of S)
        bOffV[pr] = (uint32_t)((laA + pr * 16) * 2);         // pr = d-col group (n of O)
    }

    // ---- prologue: stage Q into the two K buffers, hoist fragments ----
    {
        const int r0s = tid >> 3;
        const int qs  = (tid & 7) * 8;
#pragma unroll
        for (int p = 0; p < 4; p++) {
            int r = r0s + p * 32;
            cpa16(sbK0 + (uint32_t)(r * FST + qs) * 2, &Qp[(size_t)(q0 + r) * ROWQ + qs]);
        }
        cpa_commit();
        cpa_wait<0>();
        __syncthreads();
    }
    uint32_t aq[4][4];
#pragma unroll
    for (int kc = 0; kc < 4; kc++)
        ldsm_x4(aq[kc], sbK0 + pOff + kc * 32);
    __syncthreads();

    // ---- K/V staging (both natural layout; rows = seq) ----
    const int srow = tid >> 3;
    const int sq   = (tid & 7) * 8;
    auto stage_kv = [&](int kb, int buf) {
        const int kn = kb * 64;
        const uint32_t kBase = sbK0 + (uint32_t)buf * TB_H * 2;
        const uint32_t vBase = sbV0 + (uint32_t)buf * TB_H * 2;
#pragma unroll
        for (int p = 0; p < 2; p++) {
            int r = srow + p * 32;
            cpa16(kBase + (uint32_t)(r * FST + sq) * 2, &Kp[(size_t)(kn + r) * ROWK + sq]);
            cpa16(vBase + (uint32_t)(r * FST + sq) * 2, &Vp[(size_t)(kn + r) * ROWK + sq]);
        }
    };

    float m_i[2] = {-1e30f, -1e30f};
    float lacc[4] = {0.0f, 0.0f, 0.0f, 0.0f};   // ones-MMA row-sum accumulator
    const uint32_t ONES2 = 0x3C003C00u;         // half2(1.0, 1.0)
    const uint32_t bones[2] = {ONES2, ONES2};
    float o[8][4];
#pragma unroll
    for (int nt = 0; nt < 8; nt++)
#pragma unroll
        for (int j = 0; j < 4; j++) o[nt][j] = 0.0f;

    const int kbmax = 2 * qb + 1;
    stage_kv(0, 0);
    cpa_commit();

    for (int kb = 0; kb <= kbmax; kb++) {
        const int kn  = kb * 64;
        const int buf = kb & 1;

        cpa_wait<0>();
        __syncthreads();
        if (kb < kbmax) { stage_kv(kb + 1, buf ^ 1); cpa_commit(); }

        const uint32_t kBase = sbK0 + (uint32_t)buf * TB_H * 2;
        const uint32_t vBase = sbV0 + (uint32_t)buf * TB_H * 2;

        // ---- S = (Q*SC) K^T ----
        float s[8][4];
#pragma unroll
        for (int nt = 0; nt < 8; nt++)
#pragma unroll
            for (int j = 0; j < 4; j++) s[nt][j] = 0.0f;

#pragma unroll
        for (int kc = 0; kc < 4; kc++) {
            const uint32_t kkB = kc * 32;
#pragma unroll
            for (int pr = 0; pr < 4; pr++) {
                uint32_t bfr[4];
                ldsm_x4(bfr, kBase + bOffK[pr] + kkB);
                mma_f16(s[pr * 2],     aq[kc], bfr);
                mma_f16(s[pr * 2 + 1], aq[kc], bfr + 2);
            }
        }

        // ---- online softmax: masks, max, f16x2 exp2, P -> A-fragments --------
        uint32_t pa[4][4];
        const bool diag = (kn + 63 > q0);
        {
            const int r0 = q0 + wr + g;
            const int r1 = r0 + 8;
            float mx0 = -1e30f, mx1 = -1e30f;
#pragma unroll
            for (int nt = 0; nt < 8; nt++) {
                int cc = kn + nt * 8 + 2 * tg;
                float v0 = s[nt][0], v1 = s[nt][1], v2 = s[nt][2], v3 = s[nt][3];
                if (diag) {
                    if (cc > r0)     v0 = -1e30f;
                    if (cc + 1 > r0) v1 = -1e30f;
                    if (cc > r1)     v2 = -1e30f;
                    if (cc + 1 > r1) v3 = -1e30f;
                }
                s[nt][0] = v0; s[nt][1] = v1; s[nt][2] = v2; s[nt][3] = v3;
                mx0 = fmaxf(mx0, fmaxf(v0, v1));
                mx1 = fmaxf(mx1, fmaxf(v2, v3));
            }
            mx0 = fmaxf(mx0, __shfl_xor_sync(0xffffffffu, mx0, 1));
            mx0 = fmaxf(mx0, __shfl_xor_sync(0xffffffffu, mx0, 2));
            mx1 = fmaxf(mx1, __shfl_xor_sync(0xffffffffu, mx1, 1));
            mx1 = fmaxf(mx1, __shfl_xor_sync(0xffffffffu, mx1, 2));

            float mn0 = fmaxf(m_i[0], mx0), mn1 = fmaxf(m_i[1], mx1);
            float al0 = exp2f(m_i[0] - mn0), al1 = exp2f(m_i[1] - mn1);
#pragma unroll
            for (int nt = 0; nt < 8; nt++) {
                uint32_t d01 = h2u(__floats2half2_rn(s[nt][0] - mn0, s[nt][1] - mn0));
                uint32_t d23 = h2u(__floats2half2_rn(s[nt][2] - mn1, s[nt][3] - mn1));
                uint32_t p01 = h2exp2(d01);
                uint32_t p23 = h2exp2(d23);
                const int kc = nt >> 1;
                if ((nt & 1) == 0) {
                    pa[kc][0] = p01;
                    pa[kc][1] = p23;
                } else {
                    pa[kc][2] = p01;
                    pa[kc][3] = p23;
                }
                o[nt][0] *= al0; o[nt][1] *= al0;
                o[nt][2] *= al1; o[nt][3] *= al1;
            }
            lacc[0] *= al0; lacc[1] *= al0;
            lacc[2] *= al1; lacc[3] *= al1;
            m_i[0] = mn0; m_i[1] = mn1;
        }

        // ---- l += P @ ones (tensor pipe) ----
#pragma unroll
        for (int kc = 0; kc < 4; kc++)
            mma_f16(lacc, pa[kc], bones);

        // ---- O += P V (P from registers, V via trans-LDSM from natural tile) -
#pragma unroll
        for (int kc = 0; kc < 4; kc++) {
            const uint32_t krow = (uint32_t)(kc * 16 * FST * 2);
#pragma unroll
            for (int pr = 0; pr < 4; pr++) {
                uint32_t bfr[4];
                ldsm_x4_t(bfr, vBase + krow + bOffV[pr]);
                mma_f16(o[pr * 2],     pa[kc], bfr);
                mma_f16(o[pr * 2 + 1], pa[kc], bfr + 2);
            }
        }
    }

    // ---- epilogue ----
    const float inv0 = 1.0f / lacc[0];
    const float inv1 = 1.0f / lacc[2];
    const size_t row0 = (size_t)(q0 + wr + g) * ROWQ;
    const size_t row1 = row0 + 8 * ROWQ;
#pragma unroll
    for (int nt = 0; nt < 8; nt++) {
        int cc = nt * 8 + 2 * tg;
        *reinterpret_cast<__half2*>(&Op[row0 + cc]) =
            __floats2half2_rn(o[nt][0] * inv0, o[nt][1] * inv0);
        *reinterpret_cast<__half2*>(&Op[row1 + cc]) =
            __floats2half2_rn(o[nt][2] * inv1, o[nt][3] * inv1);
    }
}

// ================= launch =====================================================
extern "C" void kernel_launch(void* const* d_in, const int* in_sizes, int n_in,
                              void* d_out, int out_size)
{
    const float* x  = (const float*)d_in[0];
    const float* Wq = (const float*)d_in[1];
    const float* Wk = (const float*)d_in[2];
    const float* Wv = (const float*)d_in[3];
    const float* Wo = (const float*)d_in[4];
    float* out = (float*)d_out;

    cudaFuncSetAttribute(flash_mma, cudaFuncAttributeMaxDynamicSharedMemorySize, FA_SMEM);
    cudaFuncSetAttribute(qkv_mma,   cudaFuncAttributeMaxDynamicSharedMemorySize, GEMM_SMEM);
    cudaFuncSetAttribute(oproj_mma, cudaFuncAttributeMaxDynamicSharedMemorySize, GEMM_SMEM);

    prep_all<<<2048 + 2560, 256>>>(x, Wq, Wk, Wv, Wo);

    qkv_mma<<<dim3(12, 32), 128, GEMM_SMEM>>>();
    flash_mma<<<dim3(32, 16), 256, FA_SMEM>>>();
    oproj_mma<<<dim3(8, 32), 128, GEMM_SMEM>>>(out);
}

// round 15
// speedup vs baseline: 1.4329x; 1.4329x over previous
#include <cuda_runtime.h>
#include <cuda_fp16.h>
#include <cstdint>

#define S_LEN  2048
#define G_GRP  2
#define EMB    1024
#define NKV    4
#define HD     64
#define MROWS  (S_LEN * G_GRP)      // 4096
#define KVW    (NKV * HD)           // 256
#define ROWQ   (G_GRP * EMB)        // 2048 (halves)
#define ROWK   (G_GRP * KVW)        // 512  (halves)

// ---------------- scratch (all fp16) ----------------
__device__ __half g_X[MROWS * EMB];
__device__ __half g_Q[MROWS * EMB];                 // pre-scaled by SC
__device__ __half g_K[MROWS * KVW];
__device__ __half g_V[MROWS * KVW];
__device__ __half g_VT[G_GRP * NKV * HD * S_LEN];   // [(grp*4+kvh)*64+d][seq]
__device__ __half g_O[MROWS * EMB];
__device__ __half g_WT[(EMB + 2 * KVW) * EMB];
__device__ __half g_WoT[EMB * EMB];

#define SC_CONST (0.125f * 1.4426950408889634f)

// ================= helpers =================
__device__ __forceinline__ uint32_t smem_u32(const void* p) {
    uint32_t a;
    asm("{ .reg .u64 t; cvta.to.shared.u64 t, %1; cvt.u32.u64 %0, t; }" : "=r"(a) : "l"(p));
    return a;
}
__device__ __forceinline__ void mma_f16(float c[4], const uint32_t a[4], const uint32_t b[2]) {
    asm volatile(
        "mma.sync.aligned.m16n8k16.row.col.f32.f16.f16.f32 "
        "{%0,%1,%2,%3}, {%4,%5,%6,%7}, {%8,%9}, {%0,%1,%2,%3};"
        : "+f"(c[0]), "+f"(c[1]), "+f"(c[2]), "+f"(c[3])
        : "r"(a[0]), "r"(a[1]), "r"(a[2]), "r"(a[3]), "r"(b[0]), "r"(b[1]));
}
__device__ __forceinline__ void ldsm_x4(uint32_t r[4], uint32_t addr) {
    asm volatile("ldmatrix.sync.aligned.m8n8.x4.shared.b16 {%0,%1,%2,%3}, [%4];"
        : "=r"(r[0]), "=r"(r[1]), "=r"(r[2]), "=r"(r[3]) : "r"(addr));
}
__device__ __forceinline__ int ldsmA_off(int lane, int stride) {
    return ((lane & 7) + ((lane >> 3) & 1) * 8) * stride + ((lane >> 4) & 1) * 8;
}
__device__ __forceinline__ int ldsmB_off(int lane, int stride) {
    return ((lane & 7) + ((lane >> 4) & 1) * 8) * stride + ((lane >> 3) & 1) * 8;
}
__device__ __forceinline__ void cpa16(uint32_t dst, const void* src) {
    asm volatile("cp.async.cg.shared.global [%0], [%1], 16;" :: "r"(dst), "l"(src));
}
__device__ __forceinline__ void cpa_commit() { asm volatile("cp.async.commit_group;"); }
template <int N>
__device__ __forceinline__ void cpa_wait() { asm volatile("cp.async.wait_group %0;" :: "n"(N)); }
__device__ __forceinline__ uint32_t h2u(__half2 h) { return *reinterpret_cast<uint32_t*>(&h); }
__device__ __forceinline__ uint32_t h2exp2(uint32_t x) {
    uint32_t r;
    asm("ex2.approx.f16x2 %0, %1;" : "=r"(r) : "r"(x));
    return r;
}

// ================= fused prep: X round + all weight transposes ===============
__global__ __launch_bounds__(256) void prep_all(
    const float* __restrict__ x,
    const float* __restrict__ Wq, const float* __restrict__ Wk,
    const float* __restrict__ Wv, const float* __restrict__ Wo)
{
    __shared__ float t[32][33];
    const int b = blockIdx.x;
    if (b < 2048) {
        size_t i = (size_t)b * 256 + threadIdx.x;
        const float4* src = reinterpret_cast<const float4*>(x) + 2 * i;
        float4 v0 = src[0], v1 = src[1];
        __half2* dst = reinterpret_cast<__half2*>(g_X) + 4 * i;
        dst[0] = __floats2half2_rn(v0.x, v0.y);
        dst[1] = __floats2half2_rn(v0.z, v0.w);
        dst[2] = __floats2half2_rn(v1.x, v1.y);
        dst[3] = __floats2half2_rn(v1.z, v1.w);
        return;
    }
    const int bb = b - 2048;
    const int bx = bb % 80;
    const int by = bb / 80;
    const float* W; __half* WT; int N; int nb;
    if (bx < 32)      { W = Wq; WT = g_WT;                               N = EMB; nb = bx; }
    else if (bx < 40) { W = Wk; WT = g_WT + (size_t)EMB * EMB;           N = KVW; nb = bx - 32; }
    else if (bx < 48) { W = Wv; WT = g_WT + (size_t)(EMB + KVW) * EMB;   N = KVW; nb = bx - 40; }
    else              { W = Wo; WT = g_WoT;                              N = EMB; nb = bx - 48; }

    const int tx  = threadIdx.x & 31;
    const int ty0 = threadIdx.x >> 5;
#pragma unroll
    for (int r = 0; r < 4; r++) {
        int ty = ty0 + r * 8;
        t[ty][tx] = W[(size_t)(by * 32 + ty) * N + nb * 32 + tx];
    }
    __syncthreads();
#pragma unroll
    for (int r = 0; r < 4; r++) {
        int ty = ty0 + r * 8;
        WT[(size_t)(nb * 32 + ty) * EMB + by * 32 + tx] = __float2half(t[tx][ty]);
    }
}

// coalesced V transpose (half): g_V[m][c] -> g_VT[(m&1)*256 + c][m>>1]
__global__ __launch_bounds__(256) void transpose_v() {
    __shared__ __half t[64][33];
    const int mt = blockIdx.x;
    const int ct = blockIdx.y;
    const int tx = threadIdx.x & 31;
    const int ty = threadIdx.x >> 5;
#pragma unroll
    for (int k = 0; k < 8; k++) {
        int ml = ty + k * 8;
        t[ml][tx] = g_V[(size_t)(mt * 64 + ml) * KVW + ct * 32 + tx];
    }
    __syncthreads();
#pragma unroll
    for (int k = 0; k < 8; k++) {
        int rs  = ty + k * 8;
        int grp = rs >> 5, c = rs & 31;
        g_VT[(size_t)(grp * 256 + ct * 32 + c) * S_LEN + mt * 32 + tx] = t[grp + 2 * tx][c];
    }
}

// ======== fp16 mma GEMM: BM x 128 CTA tile (BM = MI*32), 128 threads ========
#define AST 72
// OM: 0 = fp32 out, 1 = half out, 2 = half out * SC.  MI: 16-row m-tiles/warp.
template <int OM, int MI>
__device__ __forceinline__ void gemm_tile(
    const __half* __restrict__ A, const __half* __restrict__ BT,
    void* __restrict__ Cv, int ldc, int m0, int n0bt, int c0)
{
    constexpr int BM     = MI * 32;
    constexpr int ABUF_A = BM  * AST;     // halves
    constexpr int ABUF_B = 128 * AST;     // halves
    constexpr int PAIR   = ABUF_A + ABUF_B;

    extern __shared__ __half hsm[];
    const uint32_t sb = smem_u32(hsm);

    const int tid  = threadIdx.x;
    const int lane = tid & 31;
    const int wid  = tid >> 5;
    const int wm   = wid >> 1;
    const int wn   = wid & 1;
    const int g    = lane >> 2;
    const int tg   = lane & 3;

    float acc[MI][8][4];
#pragma unroll
    for (int mi = 0; mi < MI; mi++)
#pragma unroll
        for (int nt = 0; nt < 8; nt++)
#pragma unroll
            for (int j = 0; j < 4; j++) acc[mi][nt][j] = 0.0f;

    const int row = tid >> 3;             // 0..15
    const int q   = (tid & 7) * 8;

    auto stage = [&](int c, int buf) {
        const int k0 = c * 64;
        const uint32_t aBase = sb + (uint32_t)buf * PAIR * 2;
        const uint32_t bBase = aBase + ABUF_A * 2;
#pragma unroll
        for (int t = 0; t < BM / 16; t++) {
            int r = row + t * 16;
            cpa16(aBase + (uint32_t)(r * AST + q) * 2, &A[(size_t)(m0 + r) * EMB + k0 + q]);
        }
#pragma unroll
        for (int t = 0; t < 8; t++) {
            int r = row + t * 16;
            cpa16(bBase + (uint32_t)(r * AST + q) * 2, &BT[(size_t)(n0bt + r) * EMB + k0 + q]);
        }
    };

    uint32_t aOff[MI], bOff[4];
    {
        const int la = ldsmA_off(lane, AST);
        const int lb = ldsmB_off(lane, AST);
#pragma unroll
        for (int mi = 0; mi < MI; mi++)
            aOff[mi] = (uint32_t)(((wm * MI * 16 + mi * 16) * AST + la) * 2);
#pragma unroll
        for (int pr = 0; pr < 4; pr++)
            bOff[pr] = (uint32_t)(((wn * 64 + pr * 16) * AST + lb) * 2);
    }

    stage(0, 0); cpa_commit();

    for (int c = 0; c < 16; c++) {
        cpa_wait<0>();
        __syncthreads();
        if (c < 15) { stage(c + 1, (c + 1) & 1); cpa_commit(); }

        const uint32_t aBase = sb + (uint32_t)(c & 1) * PAIR * 2;
        const uint32_t bBase = aBase + ABUF_A * 2;
#pragma unroll
        for (int kc = 0; kc < 4; kc++) {
            const uint32_t kkB = kc * 32;
            uint32_t a[MI][4];
#pragma unroll
            for (int mi = 0; mi < MI; mi++)
                ldsm_x4(a[mi], aBase + aOff[mi] + kkB);
#pragma unroll
            for (int pr = 0; pr < 4; pr++) {
                uint32_t bfr[4];
                ldsm_x4(bfr, bBase + bOff[pr] + kkB);
#pragma unroll
                for (int mi = 0; mi < MI; mi++) {
                    mma_f16(acc[mi][pr * 2],     a[mi], bfr);
                    mma_f16(acc[mi][pr * 2 + 1], a[mi], bfr + 2);
                }
            }
        }
    }

#pragma unroll
    for (int mi = 0; mi < MI; mi++) {
        int r0 = m0 + wm * MI * 16 + mi * 16 + g;
#pragma unroll
        for (int nt = 0; nt < 8; nt++) {
            int col = c0 + wn * 64 + nt * 8 + 2 * tg;
            if (OM == 0) {
                float* C = (float*)Cv;
                *reinterpret_cast<float2*>(&C[(size_t)r0 * ldc + col]) =
                    make_float2(acc[mi][nt][0], acc[mi][nt][1]);
                *reinterpret_cast<float2*>(&C[(size_t)(r0 + 8) * ldc + col]) =
                    make_float2(acc[mi][nt][2], acc[mi][nt][3]);
            } else {
                const float m = (OM == 2) ? SC_CONST : 1.0f;
                __half* C = (__half*)Cv;
                *reinterpret_cast<__half2*>(&C[(size_t)r0 * ldc + col]) =
                    __floats2half2_rn(acc[mi][nt][0] * m, acc[mi][nt][1] * m);
                *reinterpret_cast<__half2*>(&C[(size_t)(r0 + 8) * ldc + col]) =
                    __floats2half2_rn(acc[mi][nt][2] * m, acc[mi][nt][3] * m);
            }
        }
    }
}

#define QKV_SMEM  (2 * (128 + 128) * AST * 2)   // 73728 B
#define OPRJ_SMEM (2 * (64 + 128) * AST * 2)    // 55296 B

__global__ __launch_bounds__(128, 3) void qkv_mma() {
    int nb = blockIdx.x;
    int m0 = blockIdx.y * 128;
    if (nb < 8)
        gemm_tile<2, 4>(g_X, g_WT, g_Q, EMB, m0, nb * 128, nb * 128);
    else if (nb < 10)
        gemm_tile<1, 4>(g_X, g_WT, g_K, KVW, m0, nb * 128, (nb - 8) * 128);
    else
        gemm_tile<1, 4>(g_X, g_WT, g_V, KVW, m0, nb * 128, (nb - 10) * 128);
}

// BM = 64 -> 512 CTAs, 4 CTAs/SM -> single wave
__global__ __launch_bounds__(128, 4) void oproj_mma(float* __restrict__ out) {
    gemm_tile<0, 2>(g_O, g_WoT, out, EMB, blockIdx.y * 64, blockIdx.x * 128, blockIdx.x * 128);
}

// ================= flash attention: fp16 mma, register P, f16x2 exp ==========
#define FST  72
#define TB_H (64 * FST)
#define FA_SMEM (4 * TB_H * 2)             // 36864 B

__global__ __launch_bounds__(256, 2) void flash_mma()
{
    extern __shared__ __half fsm[];
    const uint32_t sbK0 = smem_u32(fsm);
    const uint32_t sbV0 = sbK0 + 2 * TB_H * 2;

    const int tid  = threadIdx.x;
    const int lane = tid & 31;
    const int w    = tid >> 5;
    const int g    = lane >> 2;
    const int tg   = lane & 3;
    const int wr   = w * 16;

    const int gh  = blockIdx.x;
    const int qb  = (int)gridDim.y - 1 - blockIdx.y;
    const int grp = gh & 1;
    const int h   = gh >> 1;
    const int kvh = h >> 2;

    const __half* Qp  = g_Q + grp * EMB + h * HD;
    const __half* Kp  = g_K + grp * KVW + kvh * HD;
    const __half* VTp = g_VT + (size_t)((grp * 4 + kvh) * 64) * S_LEN;
    __half*       Op  = g_O + grp * EMB + h * HD;

    const int q0 = qb * 128;

    const int laA = ldsmA_off(lane, FST);
    const int laB = ldsmB_off(lane, FST);
    const uint32_t pOff = (uint32_t)((wr * FST + laA) * 2);
    uint32_t bOff[4];
#pragma unroll
    for (int pr = 0; pr < 4; pr++)
        bOff[pr] = (uint32_t)((pr * 16 * FST + laB) * 2);

    // ---- prologue: stage Q into the two K buffers, hoist fragments ----
    {
        const int r0s = tid >> 3;
        const int qs  = (tid & 7) * 8;
#pragma unroll
        for (int p = 0; p < 4; p++) {
            int r = r0s + p * 32;
            cpa16(sbK0 + (uint32_t)(r * FST + qs) * 2, &Qp[(size_t)(q0 + r) * ROWQ + qs]);
        }
        cpa_commit();
        cpa_wait<0>();
        __syncthreads();
    }
    uint32_t aq[4][4];
#pragma unroll
    for (int kc = 0; kc < 4; kc++)
        ldsm_x4(aq[kc], sbK0 + pOff + kc * 32);
    __syncthreads();

    // ---- K/VT staging ----
    const int srow = tid >> 3;
    const int sq   = (tid & 7) * 8;
    auto stage_kv = [&](int kb, int buf) {
        const int kn = kb * 64;
        const uint32_t kBase = sbK0 + (uint32_t)buf * TB_H * 2;
        const uint32_t vBase = sbV0 + (uint32_t)buf * TB_H * 2;
#pragma unroll
        for (int p = 0; p < 2; p++) {
            int r = srow + p * 32;
            cpa16(kBase + (uint32_t)(r * FST + sq) * 2, &Kp[(size_t)(kn + r) * ROWK + sq]);
            cpa16(vBase + (uint32_t)(r * FST + sq) * 2, &VTp[(size_t)r * S_LEN + kn + sq]);
        }
    };

    float m_i[2] = {-1e30f, -1e30f};
    float l_i[2] = {0.0f, 0.0f};
    float o[8][4];
#pragma unroll
    for (int nt = 0; nt < 8; nt++)
#pragma unroll
        for (int j = 0; j < 4; j++) o[nt][j] = 0.0f;

    const int kbmax = 2 * qb + 1;
    stage_kv(0, 0);
    cpa_commit();

    for (int kb = 0; kb <= kbmax; kb++) {
        const int kn  = kb * 64;
        const int buf = kb & 1;

        cpa_wait<0>();
        __syncthreads();
        if (kb < kbmax) { stage_kv(kb + 1, buf ^ 1); cpa_commit(); }

        const uint32_t kBase = sbK0 + (uint32_t)buf * TB_H * 2;
        const uint32_t vBase = sbV0 + (uint32_t)buf * TB_H * 2;

        // ---- S = (Q*SC) K^T ----
        float s[8][4];
#pragma unroll
        for (int nt = 0; nt < 8; nt++)
#pragma unroll
            for (int j = 0; j < 4; j++) s[nt][j] = 0.0f;

#pragma unroll
        for (int kc = 0; kc < 4; kc++) {
            const uint32_t kkB = kc * 32;
#pragma unroll
            for (int pr = 0; pr < 4; pr++) {
                uint32_t bfr[4];
                ldsm_x4(bfr, kBase + bOff[pr] + kkB);
                mma_f16(s[pr * 2],     aq[kc], bfr);
                mma_f16(s[pr * 2 + 1], aq[kc], bfr + 2);
            }
        }

        // ---- online softmax: fp32 subtract, f16x2 exp2, P -> A-fragments -----
        uint32_t pa[4][4];
        const bool diag = (kn + 63 > q0);
        {
            const int r0 = q0 + wr + g;
            const int r1 = r0 + 8;
            float mx0 = -1e30f, mx1 = -1e30f;
#pragma unroll
            for (int nt = 0; nt < 8; nt++) {
                int cc = kn + nt * 8 + 2 * tg;
                float v0 = s[nt][0], v1 = s[nt][1], v2 = s[nt][2], v3 = s[nt][3];
                if (diag) {
                    if (cc > r0)     v0 = -1e30f;
                    if (cc + 1 > r0) v1 = -1e30f;
                    if (cc > r1)     v2 = -1e30f;
                    if (cc + 1 > r1) v3 = -1e30f;
                }
                s[nt][0] = v0; s[nt][1] = v1; s[nt][2] = v2; s[nt][3] = v3;
                mx0 = fmaxf(mx0, fmaxf(v0, v1));
                mx1 = fmaxf(mx1, fmaxf(v2, v3));
            }
            mx0 = fmaxf(mx0, __shfl_xor_sync(0xffffffffu, mx0, 1));
            mx0 = fmaxf(mx0, __shfl_xor_sync(0xffffffffu, mx0, 2));
            mx1 = fmaxf(mx1, __shfl_xor_sync(0xffffffffu, mx1, 1));
            mx1 = fmaxf(mx1, __shfl_xor_sync(0xffffffffu, mx1, 2));

            float mn0 = fmaxf(m_i[0], mx0), mn1 = fmaxf(m_i[1], mx1);
            float al0 = exp2f(m_i[0] - mn0), al1 = exp2f(m_i[1] - mn1);
            float ps0 = 0.0f, ps1 = 0.0f;
#pragma unroll
            for (int nt = 0; nt < 8; nt++) {
                uint32_t d01 = h2u(__floats2half2_rn(s[nt][0] - mn0, s[nt][1] - mn0));
                uint32_t d23 = h2u(__floats2half2_rn(s[nt][2] - mn1, s[nt][3] - mn1));
                uint32_t p01 = h2exp2(d01);
                uint32_t p23 = h2exp2(d23);
                const int kc = nt >> 1;
                if ((nt & 1) == 0) {
                    pa[kc][0] = p01;
                    pa[kc][1] = p23;
                } else {
                    pa[kc][2] = p01;
                    pa[kc][3] = p23;
                }
                float2 f01 = __half22float2(*reinterpret_cast<__half2*>(&p01));
                float2 f23 = __half22float2(*reinterpret_cast<__half2*>(&p23));
                ps0 += f01.x + f01.y;
                ps1 += f23.x + f23.y;
                o[nt][0] *= al0; o[nt][1] *= al0;
                o[nt][2] *= al1; o[nt][3] *= al1;
            }
            ps0 += __shfl_xor_sync(0xffffffffu, ps0, 1);
            ps0 += __shfl_xor_sync(0xffffffffu, ps0, 2);
            ps1 += __shfl_xor_sync(0xffffffffu, ps1, 1);
            ps1 += __shfl_xor_sync(0xffffffffu, ps1, 2);
            l_i[0] = l_i[0] * al0 + ps0;
            l_i[1] = l_i[1] * al1 + ps1;
            m_i[0] = mn0; m_i[1] = mn1;
        }

        // ---- O += P V (P from registers, V via LDSM) ----
#pragma unroll
        for (int kc = 0; kc < 4; kc++) {
            const uint32_t kkB = kc * 32;
#pragma unroll
            for (int pr = 0; pr < 4; pr++) {
                uint32_t bfr[4];
                ldsm_x4(bfr, vBase + bOff[pr] + kkB);
                mma_f16(o[pr * 2],     pa[kc], bfr);
                mma_f16(o[pr * 2 + 1], pa[kc], bfr + 2);
            }
        }
    }

    // ---- epilogue ----
    const float inv0 = 1.0f / l_i[0];
    const float inv1 = 1.0f / l_i[1];
    const size_t row0 = (size_t)(q0 + wr + g) * ROWQ;
    const size_t row1 = row0 + 8 * ROWQ;
#pragma unroll
    for (int nt = 0; nt < 8; nt++) {
        int cc = nt * 8 + 2 * tg;
        *reinterpret_cast<__half2*>(&Op[row0 + cc]) =
            __floats2half2_rn(o[nt][0] * inv0, o[nt][1] * inv0);
        *reinterpret_cast<__half2*>(&Op[row1 + cc]) =
            __floats2half2_rn(o[nt][2] * inv1, o[nt][3] * inv1);
    }
}

// ================= launch =====================================================
extern "C" void kernel_launch(void* const* d_in, const int* in_sizes, int n_in,
                              void* d_out, int out_size)
{
    const float* x  = (const float*)d_in[0];
    const float* Wq = (const float*)d_in[1];
    const float* Wk = (const float*)d_in[2];
    const float* Wv = (const float*)d_in[3];
    const float* Wo = (const float*)d_in[4];
    float* out = (float*)d_out;

    cudaFuncSetAttribute(flash_mma, cudaFuncAttributeMaxDynamicSharedMemorySize, FA_SMEM);
    cudaFuncSetAttribute(qkv_mma,   cudaFuncAttributeMaxDynamicSharedMemorySize, QKV_SMEM);
    cudaFuncSetAttribute(oproj_mma, cudaFuncAttributeMaxDynamicSharedMemorySize, OPRJ_SMEM);

    prep_all<<<2048 + 2560, 256>>>(x, Wq, Wk, Wv, Wo);

    qkv_mma<<<dim3(12, 32), 128, QKV_SMEM>>>();
    transpose_v<<<dim3(64, 8), 256>>>();
    flash_mma<<<dim3(32, 16), 256, FA_SMEM>>>();
    oproj_mma<<<dim3(8, 64), 128, OPRJ_SMEM>>>(out);
}

// round 16
// speedup vs baseline: 1.4753x; 1.0296x over previous
#include <cuda_runtime.h>
#include <cuda_fp16.h>
#include <cstdint>

#define S_LEN  2048
#define G_GRP  2
#define EMB    1024
#define NKV    4
#define HD     64
#define MROWS  (S_LEN * G_GRP)      // 4096
#define KVW    (NKV * HD)           // 256
#define ROWQ   (G_GRP * EMB)        // 2048 (halves)
#define ROWK   (G_GRP * KVW)        // 512  (halves)

// ---------------- scratch (all fp16) ----------------
__device__ __half g_X[MROWS * EMB];
__device__ __half g_Q[MROWS * EMB];                 // pre-scaled by SC
__device__ __half g_K[MROWS * KVW];
__device__ __half g_V[MROWS * KVW];
__device__ __half g_VT[G_GRP * NKV * HD * S_LEN];   // [(grp*4+kvh)*64+d][seq]
__device__ __half g_O[MROWS * EMB];
__device__ __half g_WT[(EMB + 2 * KVW) * EMB];
__device__ __half g_WoT[EMB * EMB];

#define SC_CONST (0.125f * 1.4426950408889634f)

// ================= helpers =================
__device__ __forceinline__ uint32_t smem_u32(const void* p) {
    uint32_t a;
    asm("{ .reg .u64 t; cvta.to.shared.u64 t, %1; cvt.u32.u64 %0, t; }" : "=r"(a) : "l"(p));
    return a;
}
__device__ __forceinline__ void mma_f16(float c[4], const uint32_t a[4], const uint32_t b[2]) {
    asm volatile(
        "mma.sync.aligned.m16n8k16.row.col.f32.f16.f16.f32 "
        "{%0,%1,%2,%3}, {%4,%5,%6,%7}, {%8,%9}, {%0,%1,%2,%3};"
        : "+f"(c[0]), "+f"(c[1]), "+f"(c[2]), "+f"(c[3])
        : "r"(a[0]), "r"(a[1]), "r"(a[2]), "r"(a[3]), "r"(b[0]), "r"(b[1]));
}
__device__ __forceinline__ void ldsm_x4(uint32_t r[4], uint32_t addr) {
    asm volatile("ldmatrix.sync.aligned.m8n8.x4.shared.b16 {%0,%1,%2,%3}, [%4];"
        : "=r"(r[0]), "=r"(r[1]), "=r"(r[2]), "=r"(r[3]) : "r"(addr));
}
__device__ __forceinline__ int ldsmA_off(int lane, int stride) {
    return ((lane & 7) + ((lane >> 3) & 1) * 8) * stride + ((lane >> 4) & 1) * 8;
}
__device__ __forceinline__ int ldsmB_off(int lane, int stride) {
    return ((lane & 7) + ((lane >> 4) & 1) * 8) * stride + ((lane >> 3) & 1) * 8;
}
__device__ __forceinline__ void cpa16(uint32_t dst, const void* src) {
    asm volatile("cp.async.cg.shared.global [%0], [%1], 16;" :: "r"(dst), "l"(src));
}
__device__ __forceinline__ void cpa_commit() { asm volatile("cp.async.commit_group;"); }
template <int N>
__device__ __forceinline__ void cpa_wait() { asm volatile("cp.async.wait_group %0;" :: "n"(N)); }
__device__ __forceinline__ uint32_t h2u(__half2 h) { return *reinterpret_cast<uint32_t*>(&h); }
__device__ __forceinline__ uint32_t h2exp2(uint32_t x) {
    uint32_t r;
    asm("ex2.approx.f16x2 %0, %1;" : "=r"(r) : "r"(x));
    return r;
}

// ================= fused prep: X round + all weight transposes ===============
__global__ __launch_bounds__(256) void prep_all(
    const float* __restrict__ x,
    const float* __restrict__ Wq, const float* __restrict__ Wk,
    const float* __restrict__ Wv, const float* __restrict__ Wo)
{
    __shared__ float t[32][33];
    const int b = blockIdx.x;
    if (b < 2048) {
        size_t i = (size_t)b * 256 + threadIdx.x;
        const float4* src = reinterpret_cast<const float4*>(x) + 2 * i;
        float4 v0 = src[0], v1 = src[1];
        __half2* dst = reinterpret_cast<__half2*>(g_X) + 4 * i;
        dst[0] = __floats2half2_rn(v0.x, v0.y);
        dst[1] = __floats2half2_rn(v0.z, v0.w);
        dst[2] = __floats2half2_rn(v1.x, v1.y);
        dst[3] = __floats2half2_rn(v1.z, v1.w);
        return;
    }
    const int bb = b - 2048;
    const int bx = bb % 80;
    const int by = bb / 80;
    const float* W; __half* WT; int N; int nb;
    if (bx < 32)      { W = Wq; WT = g_WT;                               N = EMB; nb = bx; }
    else if (bx < 40) { W = Wk; WT = g_WT + (size_t)EMB * EMB;           N = KVW; nb = bx - 32; }
    else if (bx < 48) { W = Wv; WT = g_WT + (size_t)(EMB + KVW) * EMB;   N = KVW; nb = bx - 40; }
    else              { W = Wo; WT = g_WoT;                              N = EMB; nb = bx - 48; }

    const int tx  = threadIdx.x & 31;
    const int ty0 = threadIdx.x >> 5;
#pragma unroll
    for (int r = 0; r < 4; r++) {
        int ty = ty0 + r * 8;
        t[ty][tx] = W[(size_t)(by * 32 + ty) * N + nb * 32 + tx];
    }
    __syncthreads();
#pragma unroll
    for (int r = 0; r < 4; r++) {
        int ty = ty0 + r * 8;
        WT[(size_t)(nb * 32 + ty) * EMB + by * 32 + tx] = __float2half(t[tx][ty]);
    }
}

// coalesced V transpose (half): g_V[m][c] -> g_VT[(m&1)*256 + c][m>>1]
__global__ __launch_bounds__(256) void transpose_v() {
    __shared__ __half t[64][33];
    const int mt = blockIdx.x;
    const int ct = blockIdx.y;
    const int tx = threadIdx.x & 31;
    const int ty = threadIdx.x >> 5;
#pragma unroll
    for (int k = 0; k < 8; k++) {
        int ml = ty + k * 8;
        t[ml][tx] = g_V[(size_t)(mt * 64 + ml) * KVW + ct * 32 + tx];
    }
    __syncthreads();
#pragma unroll
    for (int k = 0; k < 8; k++) {
        int rs  = ty + k * 8;
        int grp = rs >> 5, c = rs & 31;
        g_VT[(size_t)(grp * 256 + ct * 32 + c) * S_LEN + mt * 32 + tx] = t[grp + 2 * tx][c];
    }
}

// ================= fp16 mma GEMM: 128x128 CTA, 64x64 warp tile ==============
#define AST 72
#define ABUF_H (128 * AST)
#define GEMM_SMEM (4 * ABUF_H * 2)    // 73728 B

// OM: 0 = fp32 out, 1 = half out, 2 = half out * SC
template <int OM>
__device__ __forceinline__ void gemm_tile(
    const __half* __restrict__ A, const __half* __restrict__ BT,
    void* __restrict__ Cv, int ldc, int m0, int n0bt, int c0)
{
    extern __shared__ __half hsm[];
    const uint32_t sb = smem_u32(hsm);

    const int tid  = threadIdx.x;
    const int lane = tid & 31;
    const int wid  = tid >> 5;
    const int wm   = wid >> 1;
    const int wn   = wid & 1;
    const int g    = lane >> 2;
    const int tg   = lane & 3;

    float acc[4][8][4];
#pragma unroll
    for (int mi = 0; mi < 4; mi++)
#pragma unroll
        for (int nt = 0; nt < 8; nt++)
#pragma unroll
            for (int j = 0; j < 4; j++) acc[mi][nt][j] = 0.0f;

    const int row = tid >> 3;
    const int q   = (tid & 7) * 8;

    auto stage = [&](int c, int buf) {
        const int k0 = c * 64;
        const uint32_t aBase = sb + (uint32_t)(2 * buf) * ABUF_H * 2;
        const uint32_t bBase = aBase + ABUF_H * 2;
#pragma unroll
        for (int t = 0; t < 8; t++) {
            int r = row + t * 16;
            cpa16(aBase + (uint32_t)(r * AST + q) * 2, &A [(size_t)(m0 + r) * EMB + k0 + q]);
            cpa16(bBase + (uint32_t)(r * AST + q) * 2, &BT[(size_t)(n0bt + r) * EMB + k0 + q]);
        }
    };

    uint32_t aOff[4], bOff[4];
    {
        const int la = ldsmA_off(lane, AST);
        const int lb = ldsmB_off(lane, AST);
#pragma unroll
        for (int mi = 0; mi < 4; mi++)
            aOff[mi] = (uint32_t)(((wm * 64 + mi * 16) * AST + la) * 2);
#pragma unroll
        for (int pr = 0; pr < 4; pr++)
            bOff[pr] = (uint32_t)(((wn * 64 + pr * 16) * AST + lb) * 2);
    }

    stage(0, 0); cpa_commit();

    for (int c = 0; c < 16; c++) {
        cpa_wait<0>();
        __syncthreads();
        if (c < 15) { stage(c + 1, (c + 1) & 1); cpa_commit(); }

        const uint32_t aBase = sb + (uint32_t)(2 * (c & 1)) * ABUF_H * 2;
        const uint32_t bBase = aBase + ABUF_H * 2;
#pragma unroll
        for (int kc = 0; kc < 4; kc++) {
            const uint32_t kkB = kc * 32;
            uint32_t a[4][4];
#pragma unroll
            for (int mi = 0; mi < 4; mi++)
                ldsm_x4(a[mi], aBase + aOff[mi] + kkB);
#pragma unroll
            for (int pr = 0; pr < 4; pr++) {
                uint32_t bfr[4];
                ldsm_x4(bfr, bBase + bOff[pr] + kkB);
#pragma unroll
                for (int mi = 0; mi < 4; mi++) {
                    mma_f16(acc[mi][pr * 2],     a[mi], bfr);
                    mma_f16(acc[mi][pr * 2 + 1], a[mi], bfr + 2);
                }
            }
        }
    }

#pragma unroll
    for (int mi = 0; mi < 4; mi++) {
        int r0 = m0 + wm * 64 + mi * 16 + g;
#pragma unroll
        for (int nt = 0; nt < 8; nt++) {
            int col = c0 + wn * 64 + nt * 8 + 2 * tg;
            if (OM == 0) {
                float* C = (float*)Cv;
                *reinterpret_cast<float2*>(&C[(size_t)r0 * ldc + col]) =
                    make_float2(acc[mi][nt][0], acc[mi][nt][1]);
                *reinterpret_cast<float2*>(&C[(size_t)(r0 + 8) * ldc + col]) =
                    make_float2(acc[mi][nt][2], acc[mi][nt][3]);
            } else {
                const float m = (OM == 2) ? SC_CONST : 1.0f;
                __half* C = (__half*)Cv;
                *reinterpret_cast<__half2*>(&C[(size_t)r0 * ldc + col]) =
                    __floats2half2_rn(acc[mi][nt][0] * m, acc[mi][nt][1] * m);
                *reinterpret_cast<__half2*>(&C[(size_t)(r0 + 8) * ldc + col]) =
                    __floats2half2_rn(acc[mi][nt][2] * m, acc[mi][nt][3] * m);
            }
        }
    }
}

__global__ __launch_bounds__(128, 3) void qkv_mma() {
    int nb = blockIdx.x;
    int m0 = blockIdx.y * 128;
    if (nb < 8)
        gemm_tile<2>(g_X, g_WT, g_Q, EMB, m0, nb * 128, nb * 128);
    else if (nb < 10)
        gemm_tile<1>(g_X, g_WT, g_K, KVW, m0, nb * 128, (nb - 8) * 128);
    else
        gemm_tile<1>(g_X, g_WT, g_V, KVW, m0, nb * 128, (nb - 10) * 128);
}

__global__ __launch_bounds__(128, 3) void oproj_mma(float* __restrict__ out) {
    gemm_tile<0>(g_O, g_WoT, out, EMB, blockIdx.y * 128, blockIdx.x * 128, blockIdx.x * 128);
}

// ================= flash attention: fp16 mma, register P, f16x2 exp ==========
#define FST  72
#define TB_H (64 * FST)
#define FA_SMEM (4 * TB_H * 2)             // 36864 B

__global__ __launch_bounds__(256, 2) void flash_mma()
{
    extern __shared__ __half fsm[];
    const uint32_t sbK0 = smem_u32(fsm);
    const uint32_t sbV0 = sbK0 + 2 * TB_H * 2;

    const int tid  = threadIdx.x;
    const int lane = tid & 31;
    const int w    = tid >> 5;
    const int g    = lane >> 2;
    const int tg   = lane & 3;
    const int wr   = w * 16;

    const int gh  = blockIdx.x;
    const int qb  = (int)gridDim.y - 1 - blockIdx.y;
    const int grp = gh & 1;
    const int h   = gh >> 1;
    const int kvh = h >> 2;

    const __half* Qp  = g_Q + grp * EMB + h * HD;
    const __half* Kp  = g_K + grp * KVW + kvh * HD;
    const __half* VTp = g_VT + (size_t)((grp * 4 + kvh) * 64) * S_LEN;
    __half*       Op  = g_O + grp * EMB + h * HD;

    const int q0 = qb * 128;

    const int laA = ldsmA_off(lane, FST);
    const int laB = ldsmB_off(lane, FST);
    const uint32_t pOff = (uint32_t)((wr * FST + laA) * 2);
    uint32_t bOff[4];
#pragma unroll
    for (int pr = 0; pr < 4; pr++)
        bOff[pr] = (uint32_t)((pr * 16 * FST + laB) * 2);

    // ---- prologue: stage Q into the two K buffers, hoist fragments ----
    {
        const int r0s = tid >> 3;
        const int qs  = (tid & 7) * 8;
#pragma unroll
        for (int p = 0; p < 4; p++) {
            int r = r0s + p * 32;
            cpa16(sbK0 + (uint32_t)(r * FST + qs) * 2, &Qp[(size_t)(q0 + r) * ROWQ + qs]);
        }
        cpa_commit();
        cpa_wait<0>();
        __syncthreads();
    }
    uint32_t aq[4][4];
#pragma unroll
    for (int kc = 0; kc < 4; kc++)
        ldsm_x4(aq[kc], sbK0 + pOff + kc * 32);
    __syncthreads();

    // ---- K/VT staging ----
    const int srow = tid >> 3;
    const int sq   = (tid & 7) * 8;
    auto stage_kv = [&](int kb, int buf) {
        const int kn = kb * 64;
        const uint32_t kBase = sbK0 + (uint32_t)buf * TB_H * 2;
        const uint32_t vBase = sbV0 + (uint32_t)buf * TB_H * 2;
#pragma unroll
        for (int p = 0; p < 2; p++) {
            int r = srow + p * 32;
            cpa16(kBase + (uint32_t)(r * FST + sq) * 2, &Kp[(size_t)(kn + r) * ROWK + sq]);
            cpa16(vBase + (uint32_t)(r * FST + sq) * 2, &VTp[(size_t)r * S_LEN + kn + sq]);
        }
    };

    float m_i[2] = {-1e30f, -1e30f};
    float lp0 = 0.0f, lp1 = 0.0f;          // per-thread partial sums (reduced at end)
    float o[8][4];
#pragma unroll
    for (int nt = 0; nt < 8; nt++)
#pragma unroll
        for (int j = 0; j < 4; j++) o[nt][j] = 0.0f;

    const int kbmax = 2 * qb + 1;
    stage_kv(0, 0);
    cpa_commit();

    for (int kb = 0; kb <= kbmax; kb++) {
        const int kn  = kb * 64;
        const int buf = kb & 1;

        cpa_wait<0>();
        __syncthreads();
        if (kb < kbmax) { stage_kv(kb + 1, buf ^ 1); cpa_commit(); }

        const uint32_t kBase = sbK0 + (uint32_t)buf * TB_H * 2;
        const uint32_t vBase = sbV0 + (uint32_t)buf * TB_H * 2;

        // ---- S = (Q*SC) K^T ----
        float s[8][4];
#pragma unroll
        for (int nt = 0; nt < 8; nt++)
#pragma unroll
            for (int j = 0; j < 4; j++) s[nt][j] = 0.0f;

#pragma unroll
        for (int kc = 0; kc < 4; kc++) {
            const uint32_t kkB = kc * 32;
#pragma unroll
            for (int pr = 0; pr < 4; pr++) {
                uint32_t bfr[4];
                ldsm_x4(bfr, kBase + bOff[pr] + kkB);
                mma_f16(s[pr * 2],     aq[kc], bfr);
                mma_f16(s[pr * 2 + 1], aq[kc], bfr + 2);
            }
        }

        // ---- online softmax: half2 max butterfly, f16x2 exp2, reg P ----------
        uint32_t pa[4][4];
        const bool diag = (kn + 63 > q0);
        {
            const int r0 = q0 + wr + g;
            const int r1 = r0 + 8;
            float mx0 = -1e30f, mx1 = -1e30f;
#pragma unroll
            for (int nt = 0; nt < 8; nt++) {
                int cc = kn + nt * 8 + 2 * tg;
                float v0 = s[nt][0], v1 = s[nt][1], v2 = s[nt][2], v3 = s[nt][3];
                if (diag) {
                    if (cc > r0)     v0 = -1e30f;
                    if (cc + 1 > r0) v1 = -1e30f;
                    if (cc > r1)     v2 = -1e30f;
                    if (cc + 1 > r1) v3 = -1e30f;
                }
                s[nt][0] = v0; s[nt][1] = v1; s[nt][2] = v2; s[nt][3] = v3;
                mx0 = fmaxf(mx0, fmaxf(v0, v1));
                mx1 = fmaxf(mx1, fmaxf(v2, v3));
            }
            // packed half2 butterfly (2 shuffles instead of 4)
            __half2 mxh = __floats2half2_rn(mx0, mx1);
            uint32_t mxu = h2u(mxh);
            uint32_t t1  = __shfl_xor_sync(0xffffffffu, mxu, 1);
            mxh = __hmax2(mxh, *reinterpret_cast<__half2*>(&t1));
            mxu = h2u(mxh);
            uint32_t t2  = __shfl_xor_sync(0xffffffffu, mxu, 2);
            mxh = __hmax2(mxh, *reinterpret_cast<__half2*>(&t2));
            float2 mxf = __half22float2(mxh);

            float mn0 = fmaxf(m_i[0], mxf.x), mn1 = fmaxf(m_i[1], mxf.y);
            float al0 = exp2f(m_i[0] - mn0), al1 = exp2f(m_i[1] - mn1);
            float ps0 = 0.0f, ps1 = 0.0f;
#pragma unroll
            for (int nt = 0; nt < 8; nt++) {
                uint32_t d01 = h2u(__floats2half2_rn(s[nt][0] - mn0, s[nt][1] - mn0));
                uint32_t d23 = h2u(__floats2half2_rn(s[nt][2] - mn1, s[nt][3] - mn1));
                uint32_t p01 = h2exp2(d01);
                uint32_t p23 = h2exp2(d23);
                const int kc = nt >> 1;
                if ((nt & 1) == 0) {
                    pa[kc][0] = p01;
                    pa[kc][1] = p23;
                } else {
                    pa[kc][2] = p01;
                    pa[kc][3] = p23;
                }
                float2 f01 = __half22float2(*reinterpret_cast<__half2*>(&p01));
                float2 f23 = __half22float2(*reinterpret_cast<__half2*>(&p23));
                ps0 += f01.x + f01.y;
                ps1 += f23.x + f23.y;
                o[nt][0] *= al0; o[nt][1] *= al0;
                o[nt][2] *= al1; o[nt][3] *= al1;
            }
            // per-thread partial l (NO shuffles here; reduced in epilogue)
            lp0 = lp0 * al0 + ps0;
            lp1 = lp1 * al1 + ps1;
            m_i[0] = mn0; m_i[1] = mn1;
        }

        // ---- O += P V (P from registers, V via LDSM) ----
#pragma unroll
        for (int kc = 0; kc < 4; kc++) {
            const uint32_t kkB = kc * 32;
#pragma unroll
            for (int pr = 0; pr < 4; pr++) {
                uint32_t bfr[4];
                ldsm_x4(bfr, vBase + bOff[pr] + kkB);
                mma_f16(o[pr * 2],     pa[kc], bfr);
                mma_f16(o[pr * 2 + 1], pa[kc], bfr + 2);
            }
        }
    }

    // ---- epilogue: reduce l across the quad, normalize, write ----
    lp0 += __shfl_xor_sync(0xffffffffu, lp0, 1);
    lp0 += __shfl_xor_sync(0xffffffffu, lp0, 2);
    lp1 += __shfl_xor_sync(0xffffffffu, lp1, 1);
    lp1 += __shfl_xor_sync(0xffffffffu, lp1, 2);
    const float inv0 = 1.0f / lp0;
    const float inv1 = 1.0f / lp1;
    const size_t row0 = (size_t)(q0 + wr + g) * ROWQ;
    const size_t row1 = row0 + 8 * ROWQ;
#pragma unroll
    for (int nt = 0; nt < 8; nt++) {
        int cc = nt * 8 + 2 * tg;
        *reinterpret_cast<__half2*>(&Op[row0 + cc]) =
            __floats2half2_rn(o[nt][0] * inv0, o[nt][1] * inv0);
        *reinterpret_cast<__half2*>(&Op[row1 + cc]) =
            __floats2half2_rn(o[nt][2] * inv1, o[nt][3] * inv1);
    }
}

// ================= launch =====================================================
extern "C" void kernel_launch(void* const* d_in, const int* in_sizes, int n_in,
                              void* d_out, int out_size)
{
    const float* x  = (const float*)d_in[0];
    const float* Wq = (const float*)d_in[1];
    const float* Wk = (const float*)d_in[2];
    const float* Wv = (const float*)d_in[3];
    const float* Wo = (const float*)d_in[4];
    float* out = (float*)d_out;

    cudaFuncSetAttribute(flash_mma, cudaFuncAttributeMaxDynamicSharedMemorySize, FA_SMEM);
    cudaFuncSetAttribute(qkv_mma,   cudaFuncAttributeMaxDynamicSharedMemorySize, GEMM_SMEM);
    cudaFuncSetAttribute(oproj_mma, cudaFuncAttributeMaxDynamicSharedMemorySize, GEMM_SMEM);

    prep_all<<<2048 + 2560, 256>>>(x, Wq, Wk, Wv, Wo);

    qkv_mma<<<dim3(12, 32), 128, GEMM_SMEM>>>();
    transpose_v<<<dim3(64, 8), 256>>>();
    flash_mma<<<dim3(32, 16), 256, FA_SMEM>>>();
    oproj_mma<<<dim3(8, 32), 128, GEMM_SMEM>>>(out);
}